// round 11
// baseline (speedup 1.0000x reference)
#include <cuda_runtime.h>
#include <math.h>

#define NT      256
#define CHUNKS  8
#define MAXPART 4096
#define MAXB    256

__device__ float g_v1[MAXPART];
__device__ float g_v2[MAXPART];
__device__ int   g_i1[MAXPART];
__device__ unsigned int g_count;   // zero-init; reset by final block each run

// Bitwise-match jnp.nan_to_num: NaN -> 0, +-inf -> +-FLT_MAX
__device__ __forceinline__ float nan_to_num_f(float x) {
    if (isnan(x)) return 0.0f;
    return fminf(fmaxf(x, -3.402823466385288598e38f), 3.402823466385288598e38f);
}

// fast approximate score for one element (sampled path)
__device__ __forceinline__ void score_track(float x, float uraw, float inv_t,
                                            int idx, float& v1, float& v2, int& i1)
{
    const float U_LO = 1e-10f;
    const float U_HI = (float)(1.0 - 1e-7);
    float uc = fminf(fmaxf(uraw, U_LO), U_HI);
    float d  = 1.0f - uc;                          // exact near 1 (Sterbenz)
    // w ~= -log(uc): log1p cubic when d < 1/64 (accurate near uc=1), MUFU elsewhere
    float q       = fmaf(d, 0.33333334f, 0.5f);
    float w_small = d * fmaf(d, q, 1.0f);          // d + d^2/2 + d^3/3
    float w_log   = -__logf(uc);
    float w  = (d < 0.015625f) ? w_small : w_log;
    float s  = fmaf(x, inv_t, -__logf(w));         // fast score
    v2 = fmaxf(v2, fminf(s, v1));                  // top-2, branchless
    if (s > v1) { v1 = s; i1 = idx; }
}

__global__ __launch_bounds__(NT, 1)
void sampler_fused(const float* __restrict__ logits,
                   const float* __restrict__ temps,
                   const float* __restrict__ u,
                   float* __restrict__ out,
                   int V, int B)
{
    const int row   = blockIdx.x / CHUNKS;
    const int chunk = blockIdx.x % CHUNKS;
    const int V4    = V >> 2;
    const int ch4   = V4 / CHUNKS;                 // V divisible by 32; ch4 even
    const size_t row4 = (size_t)row * (size_t)V4;
    const float4* __restrict__ lg4 = (const float4*)logits + row4 + (size_t)chunk * ch4;
    const float4* __restrict__ uu4 = (const float4*)u      + row4 + (size_t)chunk * ch4;
    const int base_idx = chunk * (ch4 << 2);

    const float t = temps[row];
    const float NEG_INF = __int_as_float(0xff800000);
    float v1 = NEG_INF, v2 = NEG_INF; int i1 = 0;

    if (t <= 1e-6f) {
        // greedy: exact argmax of nan_to_num(logits); certification always passes
        for (int i = threadIdx.x * 2; i < ch4; i += NT * 2) {
            const float4 L0 = lg4[i];
            const float4 L1 = lg4[i + 1];
            const int b = base_idx + (i << 2);
            #pragma unroll
            for (int c = 0; c < 4; c++) {
                float x = nan_to_num_f((&L0.x)[c]);
                if (x > v1) { v1 = x; i1 = b + c; }
            }
            #pragma unroll
            for (int c = 0; c < 4; c++) {
                float x = nan_to_num_f((&L1.x)[c]);
                if (x > v1) { v1 = x; i1 = b + 4 + c; }
            }
        }
        v2 = NEG_INF;
    } else {
        const float t_safe = fmaxf(t, 1e-6f);
        const float inv_t  = __fdiv_rn(1.0f, t_safe);
        // unroll x2: 4 front-batched LDG.128 per iteration (MLP hiding)
        for (int i = threadIdx.x * 2; i < ch4; i += NT * 2) {
            const float4 L0 = lg4[i];
            const float4 L1 = lg4[i + 1];
            const float4 U0 = uu4[i];
            const float4 U1 = uu4[i + 1];
            const int b = base_idx + (i << 2);
            #pragma unroll
            for (int c = 0; c < 4; c++)
                score_track((&L0.x)[c], (&U0.x)[c], inv_t, b + c,     v1, v2, i1);
            #pragma unroll
            for (int c = 0; c < 4; c++)
                score_track((&L1.x)[c], (&U1.x)[c], inv_t, b + 4 + c, v1, v2, i1);
        }
    }

    // ---- block reduction: (v1,i1) max w/ lower-index tie-break; v2 = global 2nd ----
    const unsigned FULL = 0xffffffffu;
    #pragma unroll
    for (int off = 16; off > 0; off >>= 1) {
        float ov1 = __shfl_down_sync(FULL, v1, off);
        float ov2 = __shfl_down_sync(FULL, v2, off);
        int   oi  = __shfl_down_sync(FULL, i1, off);
        v2 = fmaxf(fmaxf(v2, ov2), fminf(v1, ov1));
        if (ov1 > v1 || (ov1 == v1 && oi < i1)) { v1 = ov1; i1 = oi; }
    }
    __shared__ float sv1[NT / 32], sv2[NT / 32];
    __shared__ int   si1[NT / 32];
    const int wid = threadIdx.x >> 5;
    const int lid = threadIdx.x & 31;
    if (lid == 0) { sv1[wid] = v1; sv2[wid] = v2; si1[wid] = i1; }
    __syncthreads();

    __shared__ unsigned s_rank;
    if (threadIdx.x == 0) {
        v1 = sv1[0]; v2 = sv2[0]; i1 = si1[0];
        #pragma unroll
        for (int w = 1; w < NT / 32; w++) {
            float ov1 = sv1[w], ov2 = sv2[w]; int oi = si1[w];
            v2 = fmaxf(fmaxf(v2, ov2), fminf(v1, ov1));
            if (ov1 > v1 || (ov1 == v1 && oi < i1)) { v1 = ov1; i1 = oi; }
        }
        g_v1[blockIdx.x] = v1;
        g_v2[blockIdx.x] = v2;
        g_i1[blockIdx.x] = i1;
        __threadfence();
        s_rank = atomicAdd(&g_count, 1u);
    }
    __syncthreads();
    if (s_rank != (unsigned)(gridDim.x - 1)) return;

    // =================== final block: combine + certify + rare rescan ===================
    __threadfence();  // acquire: make all blocks' partials visible

    __shared__ int   sh_fail[MAXB];
    __shared__ float sh_bv;     // running rescan max (for the rare path)
    __shared__ int   sh_bi;

    for (int r = threadIdx.x; r < B; r += NT) {
        const float NEGI = __int_as_float(0xff800000);
        float rv1 = NEGI, rv2 = NEGI; int ri1 = 0x7fffffff;
        #pragma unroll
        for (int c = 0; c < CHUNKS; c++) {
            float ov1 = g_v1[r * CHUNKS + c];
            float ov2 = g_v2[r * CHUNKS + c];
            int   oi  = g_i1[r * CHUNKS + c];
            rv2 = fmaxf(fmaxf(rv2, ov2), fminf(rv1, ov1));
            if (ov1 > rv1 || (ov1 == rv1 && oi < ri1)) { rv1 = ov1; ri1 = oi; }
        }
        const float rt = temps[r];
        const bool greedy = (rt <= 1e-6f);
        const float margin = fmaf(fabsf(rv1), 2e-6f, 1e-4f);
        // NaN-safe: NaN gap compares false -> fallback
        const bool ok = greedy || ((rv1 - rv2) > margin);
        sh_fail[r] = ok ? 0 : 1;
        if (ok) out[r] = (float)ri1;
    }
    __syncthreads();

    // exact rescan (bitwise-XLA) for each failing row, whole block per row
    for (int r = 0; r < B; r++) {
        if (!sh_fail[r]) continue;
        const float rt = temps[r];
        const float t_safe = fmaxf(rt, 1e-6f);
        const float U_LO = 1e-10f;
        const float U_HI = (float)(1.0 - 1e-7);
        const size_t roff = (size_t)r * (size_t)V;
        const float4* __restrict__ rl4 = (const float4*)(logits + roff);
        const float4* __restrict__ ru4 = (const float4*)(u + roff);
        const float NEGI = __int_as_float(0xff800000);
        float bv = NEGI; int bi = 0;
        for (int i = threadIdx.x; i < V4; i += NT) {
            const float4 L = rl4[i];
            const float4 U = ru4[i];
            const int b = i << 2;
            #pragma unroll
            for (int c = 0; c < 4; c++) {
                float x  = nan_to_num_f((&L.x)[c]);
                float uc = fminf(fmaxf((&U.x)[c], U_LO), U_HI);
                float s  = __fadd_rn(__fdiv_rn(x, t_safe), -logf(-logf(uc)));
                if (s > bv) { bv = s; bi = b + c; }
            }
        }
        #pragma unroll
        for (int off = 16; off > 0; off >>= 1) {
            float ov = __shfl_down_sync(FULL, bv, off);
            int   oi = __shfl_down_sync(FULL, bi, off);
            if (ov > bv || (ov == bv && oi < bi)) { bv = ov; bi = oi; }
        }
        if (lid == 0) { sv1[wid] = bv; si1[wid] = bi; }
        __syncthreads();
        if (threadIdx.x == 0) {
            bv = sv1[0]; bi = si1[0];
            #pragma unroll
            for (int w = 1; w < NT / 32; w++) {
                float ov = sv1[w]; int oi = si1[w];
                if (ov > bv || (ov == bv && oi < bi)) { bv = ov; bi = oi; }
            }
            sh_bv = bv; sh_bi = bi;
            out[r] = (float)bi;
        }
        __syncthreads();
    }

    // reset counter for next graph replay (deterministic across calls)
    if (threadIdx.x == 0) g_count = 0;
}

extern "C" void kernel_launch(void* const* d_in, const int* in_sizes, int n_in,
                              void* d_out, int out_size)
{
    const float* logits = (const float*)d_in[0];
    const float* temps  = (const float*)d_in[1];
    const float* u      = (const float*)d_in[2];
    float* out = (float*)d_out;

    const int B = in_sizes[1];
    const int V = in_sizes[0] / B;

    sampler_fused<<<B * CHUNKS, NT>>>(logits, temps, u, out, V, B);
}